// round 5
// baseline (speedup 1.0000x reference)
#include <cuda_runtime.h>
#include <math.h>
#include <float.h>

#define BB 2
#define NN 2048
#define CC 128
#define KK 16
#define BN_TOT (BB*NN)          // 4096
#define EPSF 1e-6f
#define BNEPS 1e-5f

// ---------------------------------------------------------------------------
// Scratch (__device__ globals; no runtime allocation)
// ---------------------------------------------------------------------------
__device__ __align__(16) float g_srcdT[BN_TOT*CC];
__device__ __align__(16) float g_dstdT[BN_TOT*CC];
__device__ float g_n2d[BN_TOT];
__device__ float g_nrm[2*BN_TOT];                 // [side][b*N+n] desc norms
__device__ __align__(16) float g_G[(long)BB*NN*NN];
__device__ int   g_idx[BN_TOT*KK];                // desc-space knn (src->dst)
__device__ int   g_knn3[2*BN_TOT*KK];             // xyz self-knn per side
__device__ float g_Msrc[BN_TOT], g_Mdst[BN_TOT], g_Mnsrc[BN_TOT], g_Mndst[BN_TOT];
__device__ float g_sdD[BN_TOT*KK], g_dsD[BN_TOT*KK], g_sdN[BN_TOT*KK], g_dsN[BN_TOT*KK];
__device__ __align__(16) float g_feat[17825792];  // nbr feats (2*65536x132) / main feats (65536x272)
__device__ __align__(16) float g_ya[16777216];    // ping
__device__ __align__(16) float g_yb[16777216];    // pong
__device__ __align__(16) float g_nbr[2*BN_TOT*CC];
__device__ float g_nbrn[2*BN_TOT];
__device__ __align__(16) float g_att[BN_TOT*256];
__device__ __align__(16) float g_h1[BN_TOT*256];
__device__ __align__(16) float g_h2[BN_TOT*256];
__device__ float g_statpart[65536];
__device__ float g_mu_nbr[3*2*CC],  g_var_nbr[3*2*CC];
__device__ float g_mu_main[3*256],  g_var_main[3*256];
__device__ float g_mu_mlp[2*256],   g_var_mlp[2*256];

// ---------------------------------------------------------------------------
// Transpose [B,C,N] -> [B,N,C]
// ---------------------------------------------------------------------------
__global__ void cr_transpose(const float* __restrict__ src, float* __restrict__ dst)
{
    __shared__ float t[32][33];
    int b  = blockIdx.z;
    int c0 = blockIdx.y * 32;
    int n0 = blockIdx.x * 32;
    #pragma unroll
    for (int r = 0; r < 32; r += 8) {
        int c = c0 + threadIdx.y + r;
        t[threadIdx.y + r][threadIdx.x] = src[((long)b*CC + c)*NN + n0 + threadIdx.x];
    }
    __syncthreads();
    #pragma unroll
    for (int r = 0; r < 32; r += 8) {
        int n = n0 + threadIdx.y + r;
        dst[((long)b*NN + n)*CC + c0 + threadIdx.x] = t[threadIdx.x][threadIdx.y + r];
    }
}

// desc norms (and squared norms for dst)
__global__ void cr_desc_norms()
{
    int s = blockIdx.y;
    int p = blockIdx.x*8 + (threadIdx.x >> 5);
    int lane = threadIdx.x & 31;
    const float* d = (s ? g_dstdT : g_srcdT) + (long)p*CC;
    float a = 0.f;
    for (int c = lane; c < CC; c += 32) { float v = d[c]; a += v*v; }
    #pragma unroll
    for (int o = 16; o; o >>= 1) a += __shfl_xor_sync(0xffffffffu, a, o);
    if (lane == 0) {
        g_nrm[s*BN_TOT + p] = sqrtf(a);
        if (s) g_n2d[p] = a;
    }
}

// ---------------------------------------------------------------------------
// Generic GEMM: Y[M,OC] = act(X[M,Kd]) @ W[OC,Kd]^T (+bias)
// act = BN(train stats, optionally 2 halves of M) + ReLU folded on A-load.
// M,OC multiples of 128. Kd multiple of 4.
// Software-pipelined: next k-tile's global loads issued before current FMA block.
// ---------------------------------------------------------------------------
__global__ void __launch_bounds__(256) cr_gemm(
    const float* __restrict__ Xb, const float* __restrict__ Wb, float* __restrict__ Yb,
    int M, int Kd, int OC,
    const float* __restrict__ amu, const float* __restrict__ avar,
    const float* __restrict__ ag,  const float* __restrict__ ab,
    int halfM, const float* __restrict__ bias,
    long xbs, long wbs, long ybs)
{
    const float* X = Xb + (long)blockIdx.z * xbs;
    const float* W = Wb + (long)blockIdx.z * wbs;
    float*       Y = Yb + (long)blockIdx.z * ybs;
    int bm = blockIdx.y * 128;
    int bn = blockIdx.x * 128;
    __shared__ __align__(16) float As[8][128];
    __shared__ __align__(16) float Bs[8][128];
    int tid = threadIdx.x;
    int lr = tid >> 1;
    int lc = (tid & 1) * 4;
    int statOff = (halfM > 0 && bm >= halfM) ? Kd : 0;
    int tx = tid & 15, ty = tid >> 4;
    float acc[8][8];
    #pragma unroll
    for (int i = 0; i < 8; i++)
        #pragma unroll
        for (int j = 0; j < 8; j++) acc[i][j] = 0.f;

    const float* xrow = X + (long)(bm + lr) * Kd;
    const float* wrow = W + (long)(bn + lr) * Kd;

    float a0=0.f,a1=0.f,a2=0.f,a3=0.f;
    float b0=0.f,b1=0.f,b2=0.f,b3=0.f;
    // prologue: load first k-tile
    {
        int kc = lc;
        if (kc + 3 < Kd) {
            float4 va = *reinterpret_cast<const float4*>(xrow + kc);
            a0=va.x; a1=va.y; a2=va.z; a3=va.w;
            float4 vb = *reinterpret_cast<const float4*>(wrow + kc);
            b0=vb.x; b1=vb.y; b2=vb.z; b3=vb.w;
        } else {
            if (kc   < Kd) { a0 = xrow[kc];   b0 = wrow[kc];   }
            if (kc+1 < Kd) { a1 = xrow[kc+1]; b1 = wrow[kc+1]; }
            if (kc+2 < Kd) { a2 = xrow[kc+2]; b2 = wrow[kc+2]; }
            if (kc+3 < Kd) { a3 = xrow[kc+3]; b3 = wrow[kc+3]; }
        }
    }

    for (int k0 = 0; k0 < Kd; k0 += 8) {
        int kc = k0 + lc;
        if (amu) {
            #pragma unroll
            for (int q = 0; q < 4; q++) {
                int c = kc + q;
                if (c < Kd) {
                    float m = amu[statOff + c];
                    float r = rsqrtf(avar[statOff + c] + BNEPS);
                    float v = (q==0? a0 : q==1? a1 : q==2? a2 : a3);
                    v = fmaxf((v - m)*r*ag[c] + ab[c], 0.f);
                    if (q==0) a0=v; else if (q==1) a1=v; else if (q==2) a2=v; else a3=v;
                }
            }
        }
        As[lc+0][lr]=a0; As[lc+1][lr]=a1; As[lc+2][lr]=a2; As[lc+3][lr]=a3;
        Bs[lc+0][lr]=b0; Bs[lc+1][lr]=b1; Bs[lc+2][lr]=b2; Bs[lc+3][lr]=b3;
        __syncthreads();

        // prefetch next k-tile (overlaps with FMA block below)
        float na0=0.f,na1=0.f,na2=0.f,na3=0.f;
        float nb0=0.f,nb1=0.f,nb2=0.f,nb3=0.f;
        if (k0 + 8 < Kd) {
            int kn = k0 + 8 + lc;
            if (kn + 3 < Kd) {
                float4 va = *reinterpret_cast<const float4*>(xrow + kn);
                na0=va.x; na1=va.y; na2=va.z; na3=va.w;
                float4 vb = *reinterpret_cast<const float4*>(wrow + kn);
                nb0=vb.x; nb1=vb.y; nb2=vb.z; nb3=vb.w;
            } else {
                if (kn   < Kd) { na0 = xrow[kn];   nb0 = wrow[kn];   }
                if (kn+1 < Kd) { na1 = xrow[kn+1]; nb1 = wrow[kn+1]; }
                if (kn+2 < Kd) { na2 = xrow[kn+2]; nb2 = wrow[kn+2]; }
                if (kn+3 < Kd) { na3 = xrow[kn+3]; nb3 = wrow[kn+3]; }
            }
        }

        #pragma unroll
        for (int kk = 0; kk < 8; kk++) {
            float4 a_lo = *reinterpret_cast<const float4*>(&As[kk][ty*8]);
            float4 a_hi = *reinterpret_cast<const float4*>(&As[kk][ty*8 + 4]);
            float4 b_lo = *reinterpret_cast<const float4*>(&Bs[kk][tx*8]);
            float4 b_hi = *reinterpret_cast<const float4*>(&Bs[kk][tx*8 + 4]);
            float ar[8] = {a_lo.x, a_lo.y, a_lo.z, a_lo.w, a_hi.x, a_hi.y, a_hi.z, a_hi.w};
            float br[8] = {b_lo.x, b_lo.y, b_lo.z, b_lo.w, b_hi.x, b_hi.y, b_hi.z, b_hi.w};
            #pragma unroll
            for (int i = 0; i < 8; i++)
                #pragma unroll
                for (int j = 0; j < 8; j++)
                    acc[i][j] += ar[i] * br[j];
        }
        __syncthreads();

        a0=na0; a1=na1; a2=na2; a3=na3;
        b0=nb0; b1=nb1; b2=nb2; b3=nb3;
    }
    #pragma unroll
    for (int i = 0; i < 8; i++) {
        int r = bm + ty*8 + i;
        float* yr = Y + (long)r*OC + bn + tx*8;
        #pragma unroll
        for (int j = 0; j < 8; j++) {
            float v = acc[i][j];
            if (bias) v += bias[bn + tx*8 + j];
            yr[j] = v;
        }
    }
}

// ---------------------------------------------------------------------------
// BN batch stats: deterministic two-stage mean/var per half
// ---------------------------------------------------------------------------
__global__ void cr_stats_partial(const float* __restrict__ Y, int rowsPerHalf, int C, int chunks)
{
    int h = blockIdx.y, ch = blockIdx.x, c = threadIdx.x;
    int rows = rowsPerHalf / chunks;
    long base = (long)h*rowsPerHalf + (long)ch*rows;
    const float* p = Y + base*C + c;
    float s = 0.f, s2 = 0.f;
    for (int r = 0; r < rows; r++) { float v = p[(long)r*C]; s += v; s2 += v*v; }
    long o = ((long)(h*chunks + ch)*2)*C + c;
    g_statpart[o]     = s;
    g_statpart[o + C] = s2;
}

__global__ void cr_stats_final(float* __restrict__ mu, float* __restrict__ var,
                               int rowsPerHalf, int C, int chunks)
{
    int h = blockIdx.x, c = threadIdx.x;
    float s = 0.f, s2 = 0.f;
    for (int ch = 0; ch < chunks; ch++) {
        long o = ((long)(h*chunks + ch)*2)*C + c;
        s += g_statpart[o]; s2 += g_statpart[o + C];
    }
    float m = s / (float)rowsPerHalf;
    mu[h*C + c]  = m;
    var[h*C + c] = fmaxf(s2 / (float)rowsPerHalf - m*m, 0.f);
}

// ---------------------------------------------------------------------------
// Top-16 smallest over shared d2[NN], smallest-index tie-break. blockDim=256.
// ---------------------------------------------------------------------------
__device__ void cr_topk16(float* sd2, float* sv, int* si, int* outIdx)
{
    int t = threadIdx.x;
    for (int k = 0; k < KK; k++) {
        float bv = FLT_MAX; int bi = NN;
        for (int j = t; j < NN; j += 256) {
            float v = sd2[j];
            if (v < bv) { bv = v; bi = j; }
        }
        sv[t] = bv; si[t] = bi;
        __syncthreads();
        for (int s = 128; s > 0; s >>= 1) {
            if (t < s) {
                if (sv[t+s] < sv[t] || (sv[t+s] == sv[t] && si[t+s] < si[t])) {
                    sv[t] = sv[t+s]; si[t] = si[t+s];
                }
            }
            __syncthreads();
        }
        if (t == 0) { outIdx[k] = si[0]; sd2[si[0]] = FLT_MAX; }
        __syncthreads();
    }
}

// descriptor-space knn: d2 row from G
__global__ void cr_knn_desc()
{
    int n = blockIdx.x, b = blockIdx.y, t = threadIdx.x;
    __shared__ float sd2[NN];
    __shared__ float sv[256];
    __shared__ int   si[256];
    const float* Grow = g_G + ((long)b*NN + n)*NN;
    for (int j = t; j < NN; j += 256)
        sd2[j] = g_n2d[b*NN + j] - 2.f*Grow[j];
    __syncthreads();
    cr_topk16(sd2, sv, si, g_idx + ((long)b*NN + n)*KK);
}

// xyz self-knn
__global__ void cr_knn_xyz(const float* __restrict__ sxyz, const float* __restrict__ dxyz)
{
    int n = blockIdx.x, b = blockIdx.y, side = blockIdx.z, t = threadIdx.x;
    const float* xyz = side ? dxyz : sxyz;
    __shared__ float sd2[NN];
    __shared__ float sv[256];
    __shared__ int   si[256];
    float cx = xyz[(b*NN+n)*3+0], cy = xyz[(b*NN+n)*3+1], cz = xyz[(b*NN+n)*3+2];
    float c2 = cx*cx + cy*cy + cz*cz;
    for (int j = t; j < NN; j += 256) {
        float px = xyz[(b*NN+j)*3+0], py = xyz[(b*NN+j)*3+1], pz = xyz[(b*NN+j)*3+2];
        sd2[j] = c2 + (px*px+py*py+pz*pz) - 2.f*(cx*px+cy*py+cz*pz);
    }
    __syncthreads();
    cr_topk16(sd2, sv, si, g_knn3 + ((long)side*BN_TOT + b*NN + n)*KK);
}

// row max of cosine (over dst) -> Msrc ; mode 0=desc, 1=nbr
__global__ void cr_rowmax(int mode)
{
    int n = blockIdx.x, b = blockIdx.y, t = threadIdx.x;
    const float* nS = mode ? g_nbrn : g_nrm;
    const float* nD = nS + BN_TOT;
    float ns = nS[b*NN + n];
    const float* Grow = g_G + ((long)b*NN + n)*NN;
    float mx = -FLT_MAX;
    for (int p = t; p < NN; p += 256) {
        float v = Grow[p] / (ns*nD[b*NN + p] + EPSF);
        mx = fmaxf(mx, v);
    }
    __shared__ float red[256];
    red[t] = mx; __syncthreads();
    for (int s = 128; s > 0; s >>= 1) { if (t < s) red[t] = fmaxf(red[t], red[t+s]); __syncthreads(); }
    if (t == 0) (mode ? g_Mnsrc : g_Msrc)[b*NN + n] = red[0];
}

// column max of cosine (over src) -> Mdst
__global__ void cr_colmax(int mode)
{
    int t = threadIdx.x, b = blockIdx.y;
    int p = blockIdx.x*256 + t;
    const float* nS = mode ? g_nbrn : g_nrm;
    const float* nD = nS + BN_TOT;
    __shared__ float sns[NN];
    for (int i = t; i < NN; i += 256) sns[i] = nS[b*NN + i];
    __syncthreads();
    float nd = nD[b*NN + p];
    const float* Gb = g_G + (long)b*NN*NN;
    float mx = -FLT_MAX;
    for (int n = 0; n < NN; n++) {
        float v = Gb[(long)n*NN + p] / (sns[n]*nd + EPSF);
        mx = fmaxf(mx, v);
    }
    (mode ? g_Mndst : g_Mdst)[b*NN + p] = mx;
}

// normalized cosines at knn
__global__ void cr_cosknn(int mode)
{
    int t = threadIdx.x;
    int p = blockIdx.x*16 + (t >> 4);
    int k = t & 15;
    const float* nS = mode ? g_nbrn : g_nrm;
    const float* nD = nS + BN_TOT;
    const float* Ms = mode ? g_Mnsrc : g_Msrc;
    const float* Md = mode ? g_Mndst : g_Mdst;
    float* sd = mode ? g_sdN : g_sdD;
    float* ds = mode ? g_dsN : g_dsD;
    int b = p >> 11;
    int n = p & (NN - 1);
    int j = g_idx[p*KK + k];
    float c = g_G[((long)b*NN + n)*NN + j] / (nS[p]*nD[b*NN + j] + EPSF);
    sd[p*KK + k] = c / (Ms[p] + EPSF);
    ds[p*KK + k] = c / (Md[b*NN + j] + EPSF);
}

// neighborhood conv input features [.,132] = [desc(128), rela(3), dist(1)]
__global__ void cr_nbr_feat(const float* __restrict__ xyz, int side)
{
    int n = blockIdx.x, b = blockIdx.y, t = threadIdx.x;
    int p = b*NN + n;
    const float* desc = side ? g_dstdT : g_srcdT;
    const int* knn = g_knn3 + ((long)side*BN_TOT + p)*KK;
    float* feat = g_feat + ((long)side*BN_TOT + p)*KK*132;
    float cx = xyz[p*3+0], cy = xyz[p*3+1], cz = xyz[p*3+2];
    for (int k = 0; k < KK; k++) {
        int j = knn[k];
        float* f = feat + k*132;
        f[t] = desc[((long)b*NN + j)*CC + t];
        if (t < 4) {
            float dx = xyz[(b*NN+j)*3+0] - cx;
            float dy = xyz[(b*NN+j)*3+1] - cy;
            float dz = xyz[(b*NN+j)*3+2] - cz;
            float v = (t==0) ? dx : (t==1) ? dy : (t==2) ? dz : sqrtf(dx*dx+dy*dy+dz*dz);
            f[128 + t] = v;
        }
    }
}

// per-point nbr weighting + aggregation (applies BN+ReLU of conv layer 3)
__global__ void cr_nbr_final(int side, const float* __restrict__ gg, const float* __restrict__ bbias)
{
    int n = blockIdx.x, b = blockIdx.y, t = threadIdx.x;
    int p = b*NN + n;
    const float* desc = side ? g_dstdT : g_srcdT;
    const int* knn = g_knn3 + ((long)side*BN_TOT + p)*KK;
    const float* ya = g_ya + ((long)side*BN_TOT*KK)*CC;
    const float* mu  = g_mu_nbr  + 2*2*CC + side*CC;
    const float* var = g_var_nbr + 2*2*CC + side*CC;
    __shared__ float red[128];
    __shared__ float sm[KK];
    __shared__ int   sj[KK];
    if (t < KK) sj[t] = knn[t];
    float muv = mu[t], rs = rsqrtf(var[t]+BNEPS), gv = gg[t], bv = bbias[t];
    for (int k = 0; k < KK; k++) {
        float v = ya[((long)p*KK + k)*CC + t];
        v = fmaxf((v - muv)*rs*gv + bv, 0.f);
        red[t] = v; __syncthreads();
        for (int s = 64; s > 0; s >>= 1) { if (t < s) red[t] = fmaxf(red[t], red[t+s]); __syncthreads(); }
        if (t == 0) sm[k] = red[0];
        __syncthreads();
    }
    float mx = -FLT_MAX;
    for (int k = 0; k < KK; k++) mx = fmaxf(mx, sm[k]);
    float w[KK]; float s = 0.f;
    for (int k = 0; k < KK; k++) { w[k] = expf(sm[k] - mx); s += w[k]; }
    float inv = 1.f / s;
    float acc = 0.f;
    for (int k = 0; k < KK; k++) acc += w[k]*inv * desc[((long)b*NN + sj[k])*CC + t];
    g_nbr[((long)side*BN_TOT + p)*CC + t] = acc;
    red[t] = acc*acc; __syncthreads();
    for (int s2 = 64; s2 > 0; s2 >>= 1) { if (t < s2) red[t] += red[t+s2]; __syncthreads(); }
    if (t == 0) g_nbrn[side*BN_TOT + p] = sqrtf(red[0]);
}

// main conv input features [.,272]
__global__ void cr_main_feat(const float* __restrict__ sxyz, const float* __restrict__ dxyz,
                             const float* __restrict__ sw,   const float* __restrict__ dw)
{
    int n = blockIdx.x, b = blockIdx.y, t = threadIdx.x;
    int p = b*NN + n;
    __shared__ int sj[KK];
    __shared__ float cx[3];
    if (t < KK) sj[t] = g_idx[p*KK + t];
    if (t < 3)  cx[t] = sxyz[p*3 + t];
    __syncthreads();
    float wsrc = sw[p];
    for (int k = 0; k < KK; k++) {
        int j = sj[k];
        long fr = ((long)p*KK + k)*272;
        const float* dj = dxyz + (b*NN + j)*3;
        for (int c = t; c < 272; c += 256) {
            float v;
            if (c < 3) v = dj[c] - cx[c];
            else if (c == 3) {
                float a = dj[0]-cx[0], bq = dj[1]-cx[1], cq = dj[2]-cx[2];
                v = sqrtf(a*a + bq*bq + cq*cq);
            }
            else if (c < 7)   v = cx[c-4];
            else if (c < 10)  v = dj[c-7];
            else if (c < 138) v = g_srcdT[(long)p*CC + (c-10)];
            else if (c < 266) v = g_dstdT[((long)b*NN + j)*CC + (c-138)];
            else if (c == 266) v = wsrc;
            else if (c == 267) v = dw[b*NN + j];
            else if (c == 268) v = g_sdD[p*KK + k];
            else if (c == 269) v = g_dsD[p*KK + k];
            else if (c == 270) v = g_sdN[p*KK + k];
            else               v = g_dsN[p*KK + k];
            g_feat[fr + c] = v;
        }
    }
}

// attention weighting, att features, corres_xyz (applies BN+ReLU of main layer 3)
__global__ void cr_attention(const float* __restrict__ dxyz, float* __restrict__ outCorres,
                             const float* __restrict__ mu, const float* __restrict__ var,
                             const float* __restrict__ gg, const float* __restrict__ bbias)
{
    int n = blockIdx.x, b = blockIdx.y, t = threadIdx.x;
    int p = b*NN + n;
    __shared__ float sh[KK][256];
    __shared__ float red[256];
    __shared__ float sm[KK];
    __shared__ int   sj[KK];
    if (t < KK) sj[t] = g_idx[p*KK + t];
    float muv = mu[t], rs = rsqrtf(var[t]+BNEPS), gv = gg[t], bv = bbias[t];
    for (int k = 0; k < KK; k++) {
        float v = g_ya[((long)p*KK + k)*256 + t];
        v = fmaxf((v - muv)*rs*gv + bv, 0.f);
        sh[k][t] = v;
        red[t] = v; __syncthreads();
        for (int s = 128; s > 0; s >>= 1) { if (t < s) red[t] = fmaxf(red[t], red[t+s]); __syncthreads(); }
        if (t == 0) sm[k] = red[0];
        __syncthreads();
    }
    float mx = -FLT_MAX;
    for (int k = 0; k < KK; k++) mx = fmaxf(mx, sm[k]);
    float aw[KK]; float s = 0.f;
    for (int k = 0; k < KK; k++) { aw[k] = expf(sm[k] - mx); s += aw[k]; }
    float inv = 1.f / s;
    float acc = 0.f;
    for (int k = 0; k < KK; k++) acc += aw[k]*inv * sh[k][t];
    g_att[(long)p*256 + t] = acc;
    if (t < 3) {
        float c = 0.f;
        for (int k = 0; k < KK; k++) c += aw[k]*inv * dxyz[(b*NN + sj[k])*3 + t];
        outCorres[p*3 + t] = c;
    }
}

// final mlp3 + sigmoid (applies BN+ReLU of mlp2 output)
__global__ void cr_mlp3(const float* __restrict__ y2, const float* __restrict__ mu,
                        const float* __restrict__ var, const float* __restrict__ gg,
                        const float* __restrict__ bb2, const float* __restrict__ W3,
                        const float* __restrict__ b3, float* __restrict__ outw)
{
    int lane = threadIdx.x & 31;
    long row = (long)blockIdx.x*8 + (threadIdx.x >> 5);
    float s = 0.f;
    for (int c = lane; c < 256; c += 32) {
        float v = y2[row*256 + c];
        v = fmaxf((v - mu[c])*rsqrtf(var[c]+BNEPS)*gg[c] + bb2[c], 0.f);
        s += v * W3[c];
    }
    #pragma unroll
    for (int o = 16; o; o >>= 1) s += __shfl_xor_sync(0xffffffffu, s, o);
    if (lane == 0) outw[row] = 1.f / (1.f + expf(-(s + b3[0])));
}

// ---------------------------------------------------------------------------
extern "C" void kernel_launch(void* const* d_in, const int* in_sizes, int n_in,
                              void* d_out, int out_size)
{
    (void)in_sizes; (void)n_in; (void)out_size;
    const float* src_xyz  = (const float*)d_in[0];
    const float* src_desc = (const float*)d_in[1];
    const float* dst_xyz  = (const float*)d_in[2];
    const float* dst_desc = (const float*)d_in[3];
    const float* src_w    = (const float*)d_in[4];
    const float* dst_w    = (const float*)d_in[5];
    const float* c1_W0    = (const float*)d_in[6];
    const float* c1_W     = (const float*)d_in[7];
    const float* c1_g     = (const float*)d_in[8];
    const float* c1_b     = (const float*)d_in[9];
    const float* c2_W0    = (const float*)d_in[10];
    const float* c2_W     = (const float*)d_in[11];
    const float* c2_g     = (const float*)d_in[12];
    const float* c2_b     = (const float*)d_in[13];
    const float* m1_W     = (const float*)d_in[14];
    const float* m1_bias  = (const float*)d_in[15];
    const float* m1_g     = (const float*)d_in[16];
    const float* m1_b     = (const float*)d_in[17];
    const float* m2_W     = (const float*)d_in[18];
    const float* m2_bias  = (const float*)d_in[19];
    const float* m2_g     = (const float*)d_in[20];
    const float* m2_b     = (const float*)d_in[21];
    const float* m3_W     = (const float*)d_in[22];
    const float* m3_bias  = (const float*)d_in[23];
    float* out = (float*)d_out;

    float *pSrcT,*pDstT,*pG,*pFeat,*pYa,*pYb,*pNbr,*pAtt,*pH1,*pH2;
    float *pMuN,*pVaN,*pMuM,*pVaM,*pMuL,*pVaL;
    cudaGetSymbolAddress((void**)&pSrcT, g_srcdT);
    cudaGetSymbolAddress((void**)&pDstT, g_dstdT);
    cudaGetSymbolAddress((void**)&pG,    g_G);
    cudaGetSymbolAddress((void**)&pFeat, g_feat);
    cudaGetSymbolAddress((void**)&pYa,   g_ya);
    cudaGetSymbolAddress((void**)&pYb,   g_yb);
    cudaGetSymbolAddress((void**)&pNbr,  g_nbr);
    cudaGetSymbolAddress((void**)&pAtt,  g_att);
    cudaGetSymbolAddress((void**)&pH1,   g_h1);
    cudaGetSymbolAddress((void**)&pH2,   g_h2);
    cudaGetSymbolAddress((void**)&pMuN,  g_mu_nbr);
    cudaGetSymbolAddress((void**)&pVaN,  g_var_nbr);
    cudaGetSymbolAddress((void**)&pMuM,  g_mu_main);
    cudaGetSymbolAddress((void**)&pVaM,  g_var_main);
    cudaGetSymbolAddress((void**)&pMuL,  g_mu_mlp);
    cudaGetSymbolAddress((void**)&pVaL,  g_var_mlp);

    auto gemmL = [](const float* X, const float* W, float* Y, int M, int Kd, int OC,
                    const float* amu, const float* avar, const float* ag, const float* ab,
                    int halfM, const float* bias, int nb, long xbs, long wbs, long ybs) {
        dim3 g(OC/128, M/128, nb);
        cr_gemm<<<g, 256>>>(X, W, Y, M, Kd, OC, amu, avar, ag, ab, halfM, bias, xbs, wbs, ybs);
    };

    // 1. transpose descriptors + norms
    dim3 tg(NN/32, CC/32, BB), tb(32, 8);
    cr_transpose<<<tg, tb>>>(src_desc, pSrcT);
    cr_transpose<<<tg, tb>>>(dst_desc, pDstT);
    cr_desc_norms<<<dim3(BN_TOT/8, 2), 256>>>();

    // 2. descriptor similarity G[src,dst]
    gemmL(pSrcT, pDstT, pG, NN, CC, NN, 0,0,0,0, 0, 0, BB, (long)NN*CC, (long)NN*CC, (long)NN*NN);

    // 3. desc knn + cosine sims
    cr_knn_desc<<<dim3(NN, BB), 256>>>();
    cr_rowmax<<<dim3(NN, BB), 256>>>(0);
    cr_colmax<<<dim3(NN/256, BB), 256>>>(0);
    cr_cosknn<<<BN_TOT/16, 256>>>(0);

    // 4. xyz self-knn both sides
    cr_knn_xyz<<<dim3(NN, BB, 2), 256>>>(src_xyz, dst_xyz);

    // 5. neighborhood convs (both sides batched; per-side BN halves)
    cr_nbr_feat<<<dim3(NN, BB), 128>>>(src_xyz, 0);
    cr_nbr_feat<<<dim3(NN, BB), 128>>>(dst_xyz, 1);
    gemmL(pFeat, c2_W0, pYa, 2*BN_TOT*KK, 132, CC, 0,0,0,0, 0, 0, 1, 0,0,0);
    cr_stats_partial<<<dim3(64, 2), CC>>>(pYa, BN_TOT*KK, CC, 64);
    cr_stats_final<<<2, CC>>>(pMuN, pVaN, BN_TOT*KK, CC, 64);
    gemmL(pYa, c2_W, pYb, 2*BN_TOT*KK, CC, CC, pMuN, pVaN, c2_g, c2_b, BN_TOT*KK, 0, 1, 0,0,0);
    cr_stats_partial<<<dim3(64, 2), CC>>>(pYb, BN_TOT*KK, CC, 64);
    cr_stats_final<<<2, CC>>>(pMuN + 2*CC, pVaN + 2*CC, BN_TOT*KK, CC, 64);
    gemmL(pYb, c2_W + CC*CC, pYa, 2*BN_TOT*KK, CC, CC, pMuN + 2*CC, pVaN + 2*CC, c2_g + CC, c2_b + CC, BN_TOT*KK, 0, 1, 0,0,0);
    cr_stats_partial<<<dim3(64, 2), CC>>>(pYa, BN_TOT*KK, CC, 64);
    cr_stats_final<<<2, CC>>>(pMuN + 4*CC, pVaN + 4*CC, BN_TOT*KK, CC, 64);
    cr_nbr_final<<<dim3(NN, BB), 128>>>(0, c2_g + 2*CC, c2_b + 2*CC);
    cr_nbr_final<<<dim3(NN, BB), 128>>>(1, c2_g + 2*CC, c2_b + 2*CC);

    // 6. nbr similarity + sims (overwrites g_G)
    gemmL(pNbr, pNbr + (long)BN_TOT*CC, pG, NN, CC, NN, 0,0,0,0, 0, 0, BB, (long)NN*CC, (long)NN*CC, (long)NN*NN);
    cr_rowmax<<<dim3(NN, BB), 256>>>(1);
    cr_colmax<<<dim3(NN/256, BB), 256>>>(1);
    cr_cosknn<<<BN_TOT/16, 256>>>(1);

    // 7. main features + convs
    cr_main_feat<<<dim3(NN, BB), 256>>>(src_xyz, dst_xyz, src_w, dst_w);
    gemmL(pFeat, c1_W0, pYa, BN_TOT*KK, 272, 256, 0,0,0,0, 0, 0, 1, 0,0,0);
    cr_stats_partial<<<dim3(64, 1), 256>>>(pYa, BN_TOT*KK, 256, 64);
    cr_stats_final<<<1, 256>>>(pMuM, pVaM, BN_TOT*KK, 256, 64);
    gemmL(pYa, c1_W, pYb, BN_TOT*KK, 256, 256, pMuM, pVaM, c1_g, c1_b, 0, 0, 1, 0,0,0);
    cr_stats_partial<<<dim3(64, 1), 256>>>(pYb, BN_TOT*KK, 256, 64);
    cr_stats_final<<<1, 256>>>(pMuM + 256, pVaM + 256, BN_TOT*KK, 256, 64);
    gemmL(pYb, c1_W + 256*256, pYa, BN_TOT*KK, 256, 256, pMuM + 256, pVaM + 256, c1_g + 256, c1_b + 256, 0, 0, 1, 0,0,0);
    cr_stats_partial<<<dim3(64, 1), 256>>>(pYa, BN_TOT*KK, 256, 64);
    cr_stats_final<<<1, 256>>>(pMuM + 512, pVaM + 512, BN_TOT*KK, 256, 64);

    // 8. attention + corres_xyz
    cr_attention<<<dim3(NN, BB), 256>>>(dst_xyz, out, pMuM + 512, pVaM + 512, c1_g + 512, c1_b + 512);

    // 9. MLP head
    gemmL(pAtt, m1_W, pH1, BN_TOT, 256, 256, 0,0,0,0, 0, m1_bias, 1, 0,0,0);
    cr_stats_partial<<<dim3(16, 1), 256>>>(pH1, BN_TOT, 256, 16);
    cr_stats_final<<<1, 256>>>(pMuL, pVaL, BN_TOT, 256, 16);
    gemmL(pH1, m2_W, pH2, BN_TOT, 256, 256, pMuL, pVaL, m1_g, m1_b, 0, m2_bias, 1, 0,0,0);
    cr_stats_partial<<<dim3(16, 1), 256>>>(pH2, BN_TOT, 256, 16);
    cr_stats_final<<<1, 256>>>(pMuL + 256, pVaL + 256, BN_TOT, 256, 16);
    cr_mlp3<<<BN_TOT/8, 256>>>(pH2, pMuL + 256, pVaL + 256, m2_g, m2_b, m3_W, m3_bias, out + BN_TOT*3);
}

// round 6
// speedup vs baseline: 1.5768x; 1.5768x over previous
#include <cuda_runtime.h>
#include <math.h>
#include <float.h>

#define BB 2
#define NN 2048
#define CC 128
#define KK 16
#define BN_TOT (BB*NN)          // 4096
#define EPSF 1e-6f
#define BNEPS 1e-5f
#define NCH 16                  // colmax row-chunks

// ---------------------------------------------------------------------------
// Scratch (__device__ globals; no runtime allocation)
// ---------------------------------------------------------------------------
__device__ __align__(16) float g_srcdT[BN_TOT*CC];
__device__ __align__(16) float g_dstdT[BN_TOT*CC];
__device__ float g_n2d[BN_TOT];
__device__ float g_nrm[2*BN_TOT];                 // [side][b*N+n] desc norms
__device__ __align__(16) float g_G[(long)BB*NN*NN];
__device__ int   g_idx[BN_TOT*KK];                // desc-space knn (src->dst)
__device__ int   g_knn3[2*BN_TOT*KK];             // xyz self-knn per side
__device__ float g_Msrc[BN_TOT], g_Mdst[BN_TOT], g_Mnsrc[BN_TOT], g_Mndst[BN_TOT];
__device__ float g_sdD[BN_TOT*KK], g_dsD[BN_TOT*KK], g_sdN[BN_TOT*KK], g_dsN[BN_TOT*KK];
__device__ __align__(16) float g_feat[17825792];  // nbr feats (2*65536x132) / main feats (65536x272)
__device__ __align__(16) float g_ya[16777216];    // ping
__device__ __align__(16) float g_yb[16777216];    // pong
__device__ __align__(16) float g_nbr[2*BN_TOT*CC];
__device__ float g_nbrn[2*BN_TOT];
__device__ __align__(16) float g_att[BN_TOT*256];
__device__ __align__(16) float g_h1[BN_TOT*256];
__device__ __align__(16) float g_h2[BN_TOT*256];
__device__ float g_statpart[262144];
__device__ float g_colpart[BB*NCH*NN];
__device__ float g_mu_nbr[3*2*CC],  g_var_nbr[3*2*CC];
__device__ float g_mu_main[3*256],  g_var_main[3*256];
__device__ float g_mu_mlp[2*256],   g_var_mlp[2*256];

// ---------------------------------------------------------------------------
// Transpose [B,C,N] -> [B,N,C]
// ---------------------------------------------------------------------------
__global__ void cr_transpose(const float* __restrict__ src, float* __restrict__ dst)
{
    __shared__ float t[32][33];
    int b  = blockIdx.z;
    int c0 = blockIdx.y * 32;
    int n0 = blockIdx.x * 32;
    #pragma unroll
    for (int r = 0; r < 32; r += 8) {
        int c = c0 + threadIdx.y + r;
        t[threadIdx.y + r][threadIdx.x] = src[((long)b*CC + c)*NN + n0 + threadIdx.x];
    }
    __syncthreads();
    #pragma unroll
    for (int r = 0; r < 32; r += 8) {
        int n = n0 + threadIdx.y + r;
        dst[((long)b*NN + n)*CC + c0 + threadIdx.x] = t[threadIdx.x][threadIdx.y + r];
    }
}

// desc norms (and squared norms for dst)
__global__ void cr_desc_norms()
{
    int s = blockIdx.y;
    int p = blockIdx.x*8 + (threadIdx.x >> 5);
    int lane = threadIdx.x & 31;
    const float* d = (s ? g_dstdT : g_srcdT) + (long)p*CC;
    float a = 0.f;
    for (int c = lane; c < CC; c += 32) { float v = d[c]; a += v*v; }
    #pragma unroll
    for (int o = 16; o; o >>= 1) a += __shfl_xor_sync(0xffffffffu, a, o);
    if (lane == 0) {
        g_nrm[s*BN_TOT + p] = sqrtf(a);
        if (s) g_n2d[p] = a;
    }
}

// ---------------------------------------------------------------------------
// Generic GEMM: Y[M,OC] = act(X[M,Kd]) @ W[OC,Kd]^T (+bias)
// act = BN(train stats, optionally 2 halves of M) + ReLU folded on A-load.
// M,OC multiples of 128. Kd multiple of 4.
// Software-pipelined: next k-tile's global loads issued before current FMA block.
// ---------------------------------------------------------------------------
__global__ void __launch_bounds__(256) cr_gemm(
    const float* __restrict__ Xb, const float* __restrict__ Wb, float* __restrict__ Yb,
    int M, int Kd, int OC,
    const float* __restrict__ amu, const float* __restrict__ avar,
    const float* __restrict__ ag,  const float* __restrict__ ab,
    int halfM, const float* __restrict__ bias,
    long xbs, long wbs, long ybs)
{
    const float* X = Xb + (long)blockIdx.z * xbs;
    const float* W = Wb + (long)blockIdx.z * wbs;
    float*       Y = Yb + (long)blockIdx.z * ybs;
    int bm = blockIdx.y * 128;
    int bn = blockIdx.x * 128;
    __shared__ __align__(16) float As[8][128];
    __shared__ __align__(16) float Bs[8][128];
    int tid = threadIdx.x;
    int lr = tid >> 1;
    int lc = (tid & 1) * 4;
    int statOff = (halfM > 0 && bm >= halfM) ? Kd : 0;
    int tx = tid & 15, ty = tid >> 4;
    float acc[8][8];
    #pragma unroll
    for (int i = 0; i < 8; i++)
        #pragma unroll
        for (int j = 0; j < 8; j++) acc[i][j] = 0.f;

    const float* xrow = X + (long)(bm + lr) * Kd;
    const float* wrow = W + (long)(bn + lr) * Kd;

    float a0=0.f,a1=0.f,a2=0.f,a3=0.f;
    float b0=0.f,b1=0.f,b2=0.f,b3=0.f;
    // prologue: load first k-tile
    {
        int kc = lc;
        if (kc + 3 < Kd) {
            float4 va = *reinterpret_cast<const float4*>(xrow + kc);
            a0=va.x; a1=va.y; a2=va.z; a3=va.w;
            float4 vb = *reinterpret_cast<const float4*>(wrow + kc);
            b0=vb.x; b1=vb.y; b2=vb.z; b3=vb.w;
        } else {
            if (kc   < Kd) { a0 = xrow[kc];   b0 = wrow[kc];   }
            if (kc+1 < Kd) { a1 = xrow[kc+1]; b1 = wrow[kc+1]; }
            if (kc+2 < Kd) { a2 = xrow[kc+2]; b2 = wrow[kc+2]; }
            if (kc+3 < Kd) { a3 = xrow[kc+3]; b3 = wrow[kc+3]; }
        }
    }

    for (int k0 = 0; k0 < Kd; k0 += 8) {
        int kc = k0 + lc;
        if (amu) {
            #pragma unroll
            for (int q = 0; q < 4; q++) {
                int c = kc + q;
                if (c < Kd) {
                    float m = amu[statOff + c];
                    float r = rsqrtf(avar[statOff + c] + BNEPS);
                    float v = (q==0? a0 : q==1? a1 : q==2? a2 : a3);
                    v = fmaxf((v - m)*r*ag[c] + ab[c], 0.f);
                    if (q==0) a0=v; else if (q==1) a1=v; else if (q==2) a2=v; else a3=v;
                }
            }
        }
        As[lc+0][lr]=a0; As[lc+1][lr]=a1; As[lc+2][lr]=a2; As[lc+3][lr]=a3;
        Bs[lc+0][lr]=b0; Bs[lc+1][lr]=b1; Bs[lc+2][lr]=b2; Bs[lc+3][lr]=b3;
        __syncthreads();

        // prefetch next k-tile (overlaps with FMA block below)
        float na0=0.f,na1=0.f,na2=0.f,na3=0.f;
        float nb0=0.f,nb1=0.f,nb2=0.f,nb3=0.f;
        if (k0 + 8 < Kd) {
            int kn = k0 + 8 + lc;
            if (kn + 3 < Kd) {
                float4 va = *reinterpret_cast<const float4*>(xrow + kn);
                na0=va.x; na1=va.y; na2=va.z; na3=va.w;
                float4 vb = *reinterpret_cast<const float4*>(wrow + kn);
                nb0=vb.x; nb1=vb.y; nb2=vb.z; nb3=vb.w;
            } else {
                if (kn   < Kd) { na0 = xrow[kn];   nb0 = wrow[kn];   }
                if (kn+1 < Kd) { na1 = xrow[kn+1]; nb1 = wrow[kn+1]; }
                if (kn+2 < Kd) { na2 = xrow[kn+2]; nb2 = wrow[kn+2]; }
                if (kn+3 < Kd) { na3 = xrow[kn+3]; nb3 = wrow[kn+3]; }
            }
        }

        #pragma unroll
        for (int kk = 0; kk < 8; kk++) {
            float4 a_lo = *reinterpret_cast<const float4*>(&As[kk][ty*8]);
            float4 a_hi = *reinterpret_cast<const float4*>(&As[kk][ty*8 + 4]);
            float4 b_lo = *reinterpret_cast<const float4*>(&Bs[kk][tx*8]);
            float4 b_hi = *reinterpret_cast<const float4*>(&Bs[kk][tx*8 + 4]);
            float ar[8] = {a_lo.x, a_lo.y, a_lo.z, a_lo.w, a_hi.x, a_hi.y, a_hi.z, a_hi.w};
            float br[8] = {b_lo.x, b_lo.y, b_lo.z, b_lo.w, b_hi.x, b_hi.y, b_hi.z, b_hi.w};
            #pragma unroll
            for (int i = 0; i < 8; i++)
                #pragma unroll
                for (int j = 0; j < 8; j++)
                    acc[i][j] += ar[i] * br[j];
        }
        __syncthreads();

        a0=na0; a1=na1; a2=na2; a3=na3;
        b0=nb0; b1=nb1; b2=nb2; b3=nb3;
    }
    #pragma unroll
    for (int i = 0; i < 8; i++) {
        int r = bm + ty*8 + i;
        float* yr = Y + (long)r*OC + bn + tx*8;
        #pragma unroll
        for (int j = 0; j < 8; j++) {
            float v = acc[i][j];
            if (bias) v += bias[bn + tx*8 + j];
            yr[j] = v;
        }
    }
}

// ---------------------------------------------------------------------------
// BN batch stats: deterministic two-stage mean/var per half
// ---------------------------------------------------------------------------
__global__ void cr_stats_partial(const float* __restrict__ Y, int rowsPerHalf, int C, int chunks)
{
    int h = blockIdx.y, ch = blockIdx.x, c = threadIdx.x;
    int rows = rowsPerHalf / chunks;
    long base = (long)h*rowsPerHalf + (long)ch*rows;
    const float* p = Y + base*C + c;
    float s = 0.f, s2 = 0.f;
    for (int r = 0; r < rows; r++) { float v = p[(long)r*C]; s += v; s2 += v*v; }
    long o = ((long)(h*chunks + ch)*2)*C + c;
    g_statpart[o]     = s;
    g_statpart[o + C] = s2;
}

__global__ void cr_stats_final(float* __restrict__ mu, float* __restrict__ var,
                               int rowsPerHalf, int C, int chunks)
{
    int h = blockIdx.x, c = threadIdx.x;
    float s = 0.f, s2 = 0.f;
    for (int ch = 0; ch < chunks; ch++) {
        long o = ((long)(h*chunks + ch)*2)*C + c;
        s += g_statpart[o]; s2 += g_statpart[o + C];
    }
    float m = s / (float)rowsPerHalf;
    mu[h*C + c]  = m;
    var[h*C + c] = fmaxf(s2 / (float)rowsPerHalf - m*m, 0.f);
}

// ---------------------------------------------------------------------------
// Top-16 smallest over shared d2[NN], smallest-index tie-break. blockDim=256.
// 2 barriers per k (smem partials + warp-shuffle final).
// ---------------------------------------------------------------------------
__device__ void cr_topk16(float* sd2, float* sv, int* si, int* outIdx)
{
    int t = threadIdx.x;
    for (int k = 0; k < KK; k++) {
        float bv = FLT_MAX; int bi = NN;
        for (int j = t; j < NN; j += 256) {
            float v = sd2[j];
            if (v < bv) { bv = v; bi = j; }
        }
        sv[t] = bv; si[t] = bi;
        __syncthreads();
        if (t < 32) {
            #pragma unroll
            for (int o = 32; o < 256; o += 32) {
                float v2 = sv[t + o]; int i2 = si[t + o];
                if (v2 < bv || (v2 == bv && i2 < bi)) { bv = v2; bi = i2; }
            }
            #pragma unroll
            for (int o = 16; o; o >>= 1) {
                float v2 = __shfl_xor_sync(0xffffffffu, bv, o);
                int   i2 = __shfl_xor_sync(0xffffffffu, bi, o);
                if (v2 < bv || (v2 == bv && i2 < bi)) { bv = v2; bi = i2; }
            }
            if (t == 0) { outIdx[k] = bi; sd2[bi] = FLT_MAX; }
        }
        __syncthreads();
    }
}

// descriptor-space knn: d2 row from G
__global__ void cr_knn_desc()
{
    int n = blockIdx.x, b = blockIdx.y, t = threadIdx.x;
    __shared__ float sd2[NN];
    __shared__ float sv[256];
    __shared__ int   si[256];
    const float* Grow = g_G + ((long)b*NN + n)*NN;
    for (int j = t; j < NN; j += 256)
        sd2[j] = g_n2d[b*NN + j] - 2.f*Grow[j];
    __syncthreads();
    cr_topk16(sd2, sv, si, g_idx + ((long)b*NN + n)*KK);
}

// xyz self-knn
__global__ void cr_knn_xyz(const float* __restrict__ sxyz, const float* __restrict__ dxyz)
{
    int n = blockIdx.x, b = blockIdx.y, side = blockIdx.z, t = threadIdx.x;
    const float* xyz = side ? dxyz : sxyz;
    __shared__ float sd2[NN];
    __shared__ float sv[256];
    __shared__ int   si[256];
    float cx = xyz[(b*NN+n)*3+0], cy = xyz[(b*NN+n)*3+1], cz = xyz[(b*NN+n)*3+2];
    float c2 = cx*cx + cy*cy + cz*cz;
    for (int j = t; j < NN; j += 256) {
        float px = xyz[(b*NN+j)*3+0], py = xyz[(b*NN+j)*3+1], pz = xyz[(b*NN+j)*3+2];
        sd2[j] = c2 + (px*px+py*py+pz*pz) - 2.f*(cx*px+cy*py+cz*pz);
    }
    __syncthreads();
    cr_topk16(sd2, sv, si, g_knn3 + ((long)side*BN_TOT + b*NN + n)*KK);
}

// row max of cosine (over dst) -> Msrc ; mode 0=desc, 1=nbr
__global__ void cr_rowmax(int mode)
{
    int n = blockIdx.x, b = blockIdx.y, t = threadIdx.x;
    const float* nS = mode ? g_nbrn : g_nrm;
    const float* nD = nS + BN_TOT;
    float ns = nS[b*NN + n];
    const float* Grow = g_G + ((long)b*NN + n)*NN;
    float mx = -FLT_MAX;
    for (int p = t; p < NN; p += 256) {
        float v = Grow[p] / (ns*nD[b*NN + p] + EPSF);
        mx = fmaxf(mx, v);
    }
    __shared__ float red[256];
    red[t] = mx; __syncthreads();
    for (int s = 128; s > 0; s >>= 1) { if (t < s) red[t] = fmaxf(red[t], red[t+s]); __syncthreads(); }
    if (t == 0) (mode ? g_Mnsrc : g_Msrc)[b*NN + n] = red[0];
}

// column max of cosine (over src), two-stage
__global__ void cr_colmax_part(int mode)   // grid (NN/256, NCH, BB)
{
    int t = threadIdx.x, by = blockIdx.y, b = blockIdx.z;
    int p = blockIdx.x*256 + t;
    const float* nS = mode ? g_nbrn : g_nrm;
    const float* nD = nS + BN_TOT;
    __shared__ float sns[NN/NCH];
    int n0 = by*(NN/NCH);
    if (t < NN/NCH) sns[t] = nS[b*NN + n0 + t];
    __syncthreads();
    float nd = nD[b*NN + p];
    const float* Gb = g_G + (long)b*NN*NN + (long)n0*NN;
    float mx = -FLT_MAX;
    for (int n = 0; n < NN/NCH; n++) {
        float v = Gb[(long)n*NN + p] / (sns[n]*nd + EPSF);
        mx = fmaxf(mx, v);
    }
    g_colpart[((long)b*NCH + by)*NN + p] = mx;
}

__global__ void cr_colmax_fin(int mode)    // grid (NN/256, BB)
{
    int t = threadIdx.x, b = blockIdx.y;
    int p = blockIdx.x*256 + t;
    float mx = -FLT_MAX;
    #pragma unroll
    for (int c = 0; c < NCH; c++)
        mx = fmaxf(mx, g_colpart[((long)b*NCH + c)*NN + p]);
    (mode ? g_Mndst : g_Mdst)[b*NN + p] = mx;
}

// normalized cosines at knn
__global__ void cr_cosknn(int mode)
{
    int t = threadIdx.x;
    int p = blockIdx.x*16 + (t >> 4);
    int k = t & 15;
    const float* nS = mode ? g_nbrn : g_nrm;
    const float* nD = nS + BN_TOT;
    const float* Ms = mode ? g_Mnsrc : g_Msrc;
    const float* Md = mode ? g_Mndst : g_Mdst;
    float* sd = mode ? g_sdN : g_sdD;
    float* ds = mode ? g_dsN : g_dsD;
    int b = p >> 11;
    int n = p & (NN - 1);
    int j = g_idx[p*KK + k];
    float c = g_G[((long)b*NN + n)*NN + j] / (nS[p]*nD[b*NN + j] + EPSF);
    sd[p*KK + k] = c / (Ms[p] + EPSF);
    ds[p*KK + k] = c / (Md[b*NN + j] + EPSF);
}

// neighborhood conv input features [.,132] = [desc(128), rela(3), dist(1)]
__global__ void cr_nbr_feat(const float* __restrict__ xyz, int side)
{
    int n = blockIdx.x, b = blockIdx.y, t = threadIdx.x;
    int p = b*NN + n;
    const float* desc = side ? g_dstdT : g_srcdT;
    const int* knn = g_knn3 + ((long)side*BN_TOT + p)*KK;
    float* feat = g_feat + ((long)side*BN_TOT + p)*KK*132;
    float cx = xyz[p*3+0], cy = xyz[p*3+1], cz = xyz[p*3+2];
    for (int k = 0; k < KK; k++) {
        int j = knn[k];
        float* f = feat + k*132;
        f[t] = desc[((long)b*NN + j)*CC + t];
        if (t < 4) {
            float dx = xyz[(b*NN+j)*3+0] - cx;
            float dy = xyz[(b*NN+j)*3+1] - cy;
            float dz = xyz[(b*NN+j)*3+2] - cz;
            float v = (t==0) ? dx : (t==1) ? dy : (t==2) ? dz : sqrtf(dx*dx+dy*dy+dz*dz);
            f[128 + t] = v;
        }
    }
}

// per-point nbr weighting + aggregation (applies BN+ReLU of conv layer 3)
// blockDim = 128; 2 barriers total via all-k warp-parallel max.
__global__ void cr_nbr_final(int side, const float* __restrict__ gg, const float* __restrict__ bbias)
{
    int n = blockIdx.x, b = blockIdx.y, t = threadIdx.x;
    int p = b*NN + n;
    const float* desc = side ? g_dstdT : g_srcdT;
    const int* knn = g_knn3 + ((long)side*BN_TOT + p)*KK;
    const float* ya = g_ya + ((long)side*BN_TOT*KK)*CC;
    const float* mu  = g_mu_nbr  + 2*2*CC + side*CC;
    const float* var = g_var_nbr + 2*2*CC + side*CC;
    __shared__ float sh[KK][128];
    __shared__ float sm[KK];
    __shared__ int   sj[KK];
    __shared__ float part[4];
    if (t < KK) sj[t] = knn[t];
    float muv = mu[t], rs = rsqrtf(var[t]+BNEPS), gv = gg[t], bv = bbias[t];
    #pragma unroll
    for (int k = 0; k < KK; k++) {
        float v = ya[((long)p*KK + k)*CC + t];
        sh[k][t] = fmaxf((v - muv)*rs*gv + bv, 0.f);
    }
    __syncthreads();
    int w = t >> 5, lane = t & 31;
    #pragma unroll
    for (int kk = 0; kk < 4; kk++) {
        int k = w*4 + kk;
        float m = fmaxf(fmaxf(sh[k][lane], sh[k][lane+32]),
                        fmaxf(sh[k][lane+64], sh[k][lane+96]));
        #pragma unroll
        for (int o = 16; o; o >>= 1) m = fmaxf(m, __shfl_xor_sync(0xffffffffu, m, o));
        if (lane == 0) sm[k] = m;
    }
    __syncthreads();
    float mx = -FLT_MAX;
    #pragma unroll
    for (int k = 0; k < KK; k++) mx = fmaxf(mx, sm[k]);
    float wk[KK]; float s = 0.f;
    #pragma unroll
    for (int k = 0; k < KK; k++) { wk[k] = expf(sm[k] - mx); s += wk[k]; }
    float inv = 1.f / s;
    float acc = 0.f;
    #pragma unroll
    for (int k = 0; k < KK; k++) acc += wk[k]*inv * desc[((long)b*NN + sj[k])*CC + t];
    g_nbr[((long)side*BN_TOT + p)*CC + t] = acc;
    // norm: warp partial sums + cross-warp combine
    float sq = acc*acc;
    #pragma unroll
    for (int o = 16; o; o >>= 1) sq += __shfl_xor_sync(0xffffffffu, sq, o);
    if (lane == 0) part[w] = sq;
    __syncthreads();
    if (t == 0) g_nbrn[side*BN_TOT + p] = sqrtf(part[0]+part[1]+part[2]+part[3]);
}

// main conv input features [.,272]
__global__ void cr_main_feat(const float* __restrict__ sxyz, const float* __restrict__ dxyz,
                             const float* __restrict__ sw,   const float* __restrict__ dw)
{
    int n = blockIdx.x, b = blockIdx.y, t = threadIdx.x;
    int p = b*NN + n;
    __shared__ int sj[KK];
    __shared__ float cx[3];
    if (t < KK) sj[t] = g_idx[p*KK + t];
    if (t < 3)  cx[t] = sxyz[p*3 + t];
    __syncthreads();
    float wsrc = sw[p];
    for (int k = 0; k < KK; k++) {
        int j = sj[k];
        long fr = ((long)p*KK + k)*272;
        const float* dj = dxyz + (b*NN + j)*3;
        for (int c = t; c < 272; c += 256) {
            float v;
            if (c < 3) v = dj[c] - cx[c];
            else if (c == 3) {
                float a = dj[0]-cx[0], bq = dj[1]-cx[1], cq = dj[2]-cx[2];
                v = sqrtf(a*a + bq*bq + cq*cq);
            }
            else if (c < 7)   v = cx[c-4];
            else if (c < 10)  v = dj[c-7];
            else if (c < 138) v = g_srcdT[(long)p*CC + (c-10)];
            else if (c < 266) v = g_dstdT[((long)b*NN + j)*CC + (c-138)];
            else if (c == 266) v = wsrc;
            else if (c == 267) v = dw[b*NN + j];
            else if (c == 268) v = g_sdD[p*KK + k];
            else if (c == 269) v = g_dsD[p*KK + k];
            else if (c == 270) v = g_sdN[p*KK + k];
            else               v = g_dsN[p*KK + k];
            g_feat[fr + c] = v;
        }
    }
}

// attention weighting, att features, corres_xyz (applies BN+ReLU of main layer 3)
// blockDim = 256; 2 barriers via warp-parallel per-k max.
__global__ void cr_attention(const float* __restrict__ dxyz, float* __restrict__ outCorres,
                             const float* __restrict__ mu, const float* __restrict__ var,
                             const float* __restrict__ gg, const float* __restrict__ bbias)
{
    int n = blockIdx.x, b = blockIdx.y, t = threadIdx.x;
    int p = b*NN + n;
    __shared__ float sh[KK][256];
    __shared__ float sm[KK];
    __shared__ int   sj[KK];
    if (t < KK) sj[t] = g_idx[p*KK + t];
    float muv = mu[t], rs = rsqrtf(var[t]+BNEPS), gv = gg[t], bv = bbias[t];
    #pragma unroll
    for (int k = 0; k < KK; k++) {
        float v = g_ya[((long)p*KK + k)*256 + t];
        sh[k][t] = fmaxf((v - muv)*rs*gv + bv, 0.f);
    }
    __syncthreads();
    int w = t >> 5, lane = t & 31;
    #pragma unroll
    for (int kk = 0; kk < 2; kk++) {
        int k = w*2 + kk;
        float m = -FLT_MAX;
        #pragma unroll
        for (int o = 0; o < 256; o += 32) m = fmaxf(m, sh[k][lane + o]);
        #pragma unroll
        for (int o = 16; o; o >>= 1) m = fmaxf(m, __shfl_xor_sync(0xffffffffu, m, o));
        if (lane == 0) sm[k] = m;
    }
    __syncthreads();
    float mx = -FLT_MAX;
    #pragma unroll
    for (int k = 0; k < KK; k++) mx = fmaxf(mx, sm[k]);
    float aw[KK]; float s = 0.f;
    #pragma unroll
    for (int k = 0; k < KK; k++) { aw[k] = expf(sm[k] - mx); s += aw[k]; }
    float inv = 1.f / s;
    float acc = 0.f;
    #pragma unroll
    for (int k = 0; k < KK; k++) acc += aw[k]*inv * sh[k][t];
    g_att[(long)p*256 + t] = acc;
    if (t < 3) {
        float c = 0.f;
        #pragma unroll
        for (int k = 0; k < KK; k++) c += aw[k]*inv * dxyz[(b*NN + sj[k])*3 + t];
        outCorres[p*3 + t] = c;
    }
}

// final mlp3 + sigmoid (applies BN+ReLU of mlp2 output)
__global__ void cr_mlp3(const float* __restrict__ y2, const float* __restrict__ mu,
                        const float* __restrict__ var, const float* __restrict__ gg,
                        const float* __restrict__ bb2, const float* __restrict__ W3,
                        const float* __restrict__ b3, float* __restrict__ outw)
{
    int lane = threadIdx.x & 31;
    long row = (long)blockIdx.x*8 + (threadIdx.x >> 5);
    float s = 0.f;
    for (int c = lane; c < 256; c += 32) {
        float v = y2[row*256 + c];
        v = fmaxf((v - mu[c])*rsqrtf(var[c]+BNEPS)*gg[c] + bb2[c], 0.f);
        s += v * W3[c];
    }
    #pragma unroll
    for (int o = 16; o; o >>= 1) s += __shfl_xor_sync(0xffffffffu, s, o);
    if (lane == 0) outw[row] = 1.f / (1.f + expf(-(s + b3[0])));
}

// ---------------------------------------------------------------------------
extern "C" void kernel_launch(void* const* d_in, const int* in_sizes, int n_in,
                              void* d_out, int out_size)
{
    (void)in_sizes; (void)n_in; (void)out_size;
    const float* src_xyz  = (const float*)d_in[0];
    const float* src_desc = (const float*)d_in[1];
    const float* dst_xyz  = (const float*)d_in[2];
    const float* dst_desc = (const float*)d_in[3];
    const float* src_w    = (const float*)d_in[4];
    const float* dst_w    = (const float*)d_in[5];
    const float* c1_W0    = (const float*)d_in[6];
    const float* c1_W     = (const float*)d_in[7];
    const float* c1_g     = (const float*)d_in[8];
    const float* c1_b     = (const float*)d_in[9];
    const float* c2_W0    = (const float*)d_in[10];
    const float* c2_W     = (const float*)d_in[11];
    const float* c2_g     = (const float*)d_in[12];
    const float* c2_b     = (const float*)d_in[13];
    const float* m1_W     = (const float*)d_in[14];
    const float* m1_bias  = (const float*)d_in[15];
    const float* m1_g     = (const float*)d_in[16];
    const float* m1_b     = (const float*)d_in[17];
    const float* m2_W     = (const float*)d_in[18];
    const float* m2_bias  = (const float*)d_in[19];
    const float* m2_g     = (const float*)d_in[20];
    const float* m2_b     = (const float*)d_in[21];
    const float* m3_W     = (const float*)d_in[22];
    const float* m3_bias  = (const float*)d_in[23];
    float* out = (float*)d_out;

    float *pSrcT,*pDstT,*pG,*pFeat,*pYa,*pYb,*pNbr,*pAtt,*pH1,*pH2;
    float *pMuN,*pVaN,*pMuM,*pVaM,*pMuL,*pVaL;
    cudaGetSymbolAddress((void**)&pSrcT, g_srcdT);
    cudaGetSymbolAddress((void**)&pDstT, g_dstdT);
    cudaGetSymbolAddress((void**)&pG,    g_G);
    cudaGetSymbolAddress((void**)&pFeat, g_feat);
    cudaGetSymbolAddress((void**)&pYa,   g_ya);
    cudaGetSymbolAddress((void**)&pYb,   g_yb);
    cudaGetSymbolAddress((void**)&pNbr,  g_nbr);
    cudaGetSymbolAddress((void**)&pAtt,  g_att);
    cudaGetSymbolAddress((void**)&pH1,   g_h1);
    cudaGetSymbolAddress((void**)&pH2,   g_h2);
    cudaGetSymbolAddress((void**)&pMuN,  g_mu_nbr);
    cudaGetSymbolAddress((void**)&pVaN,  g_var_nbr);
    cudaGetSymbolAddress((void**)&pMuM,  g_mu_main);
    cudaGetSymbolAddress((void**)&pVaM,  g_var_main);
    cudaGetSymbolAddress((void**)&pMuL,  g_mu_mlp);
    cudaGetSymbolAddress((void**)&pVaL,  g_var_mlp);

    auto gemmL = [](const float* X, const float* W, float* Y, int M, int Kd, int OC,
                    const float* amu, const float* avar, const float* ag, const float* ab,
                    int halfM, const float* bias, int nb, long xbs, long wbs, long ybs) {
        dim3 g(OC/128, M/128, nb);
        cr_gemm<<<g, 256>>>(X, W, Y, M, Kd, OC, amu, avar, ag, ab, halfM, bias, xbs, wbs, ybs);
    };

    // 1. transpose descriptors + norms
    dim3 tg(NN/32, CC/32, BB), tb(32, 8);
    cr_transpose<<<tg, tb>>>(src_desc, pSrcT);
    cr_transpose<<<tg, tb>>>(dst_desc, pDstT);
    cr_desc_norms<<<dim3(BN_TOT/8, 2), 256>>>();

    // 2. descriptor similarity G[src,dst]
    gemmL(pSrcT, pDstT, pG, NN, CC, NN, 0,0,0,0, 0, 0, BB, (long)NN*CC, (long)NN*CC, (long)NN*NN);

    // 3. desc knn + cosine sims
    cr_knn_desc<<<dim3(NN, BB), 256>>>();
    cr_rowmax<<<dim3(NN, BB), 256>>>(0);
    cr_colmax_part<<<dim3(NN/256, NCH, BB), 256>>>(0);
    cr_colmax_fin<<<dim3(NN/256, BB), 256>>>(0);
    cr_cosknn<<<BN_TOT/16, 256>>>(0);

    // 4. xyz self-knn both sides
    cr_knn_xyz<<<dim3(NN, BB, 2), 256>>>(src_xyz, dst_xyz);

    // 5. neighborhood convs (both sides batched; per-side BN halves)
    cr_nbr_feat<<<dim3(NN, BB), 128>>>(src_xyz, 0);
    cr_nbr_feat<<<dim3(NN, BB), 128>>>(dst_xyz, 1);
    gemmL(pFeat, c2_W0, pYa, 2*BN_TOT*KK, 132, CC, 0,0,0,0, 0, 0, 1, 0,0,0);
    cr_stats_partial<<<dim3(256, 2), CC>>>(pYa, BN_TOT*KK, CC, 256);
    cr_stats_final<<<2, CC>>>(pMuN, pVaN, BN_TOT*KK, CC, 256);
    gemmL(pYa, c2_W, pYb, 2*BN_TOT*KK, CC, CC, pMuN, pVaN, c2_g, c2_b, BN_TOT*KK, 0, 1, 0,0,0);
    cr_stats_partial<<<dim3(256, 2), CC>>>(pYb, BN_TOT*KK, CC, 256);
    cr_stats_final<<<2, CC>>>(pMuN + 2*CC, pVaN + 2*CC, BN_TOT*KK, CC, 256);
    gemmL(pYb, c2_W + CC*CC, pYa, 2*BN_TOT*KK, CC, CC, pMuN + 2*CC, pVaN + 2*CC, c2_g + CC, c2_b + CC, BN_TOT*KK, 0, 1, 0,0,0);
    cr_stats_partial<<<dim3(256, 2), CC>>>(pYa, BN_TOT*KK, CC, 256);
    cr_stats_final<<<2, CC>>>(pMuN + 4*CC, pVaN + 4*CC, BN_TOT*KK, CC, 256);
    cr_nbr_final<<<dim3(NN, BB), 128>>>(0, c2_g + 2*CC, c2_b + 2*CC);
    cr_nbr_final<<<dim3(NN, BB), 128>>>(1, c2_g + 2*CC, c2_b + 2*CC);

    // 6. nbr similarity + sims (overwrites g_G)
    gemmL(pNbr, pNbr + (long)BN_TOT*CC, pG, NN, CC, NN, 0,0,0,0, 0, 0, BB, (long)NN*CC, (long)NN*CC, (long)NN*NN);
    cr_rowmax<<<dim3(NN, BB), 256>>>(1);
    cr_colmax_part<<<dim3(NN/256, NCH, BB), 256>>>(1);
    cr_colmax_fin<<<dim3(NN/256, BB), 256>>>(1);
    cr_cosknn<<<BN_TOT/16, 256>>>(1);

    // 7. main features + convs
    cr_main_feat<<<dim3(NN, BB), 256>>>(src_xyz, dst_xyz, src_w, dst_w);
    gemmL(pFeat, c1_W0, pYa, BN_TOT*KK, 272, 256, 0,0,0,0, 0, 0, 1, 0,0,0);
    cr_stats_partial<<<dim3(256, 1), 256>>>(pYa, BN_TOT*KK, 256, 256);
    cr_stats_final<<<1, 256>>>(pMuM, pVaM, BN_TOT*KK, 256, 256);
    gemmL(pYa, c1_W, pYb, BN_TOT*KK, 256, 256, pMuM, pVaM, c1_g, c1_b, 0, 0, 1, 0,0,0);
    cr_stats_partial<<<dim3(256, 1), 256>>>(pYb, BN_TOT*KK, 256, 256);
    cr_stats_final<<<1, 256>>>(pMuM + 256, pVaM + 256, BN_TOT*KK, 256, 256);
    gemmL(pYb, c1_W + 256*256, pYa, BN_TOT*KK, 256, 256, pMuM + 256, pVaM + 256, c1_g + 256, c1_b + 256, 0, 0, 1, 0,0,0);
    cr_stats_partial<<<dim3(256, 1), 256>>>(pYa, BN_TOT*KK, 256, 256);
    cr_stats_final<<<1, 256>>>(pMuM + 512, pVaM + 512, BN_TOT*KK, 256, 256);

    // 8. attention + corres_xyz
    cr_attention<<<dim3(NN, BB), 256>>>(dst_xyz, out, pMuM + 512, pVaM + 512, c1_g + 512, c1_b + 512);

    // 9. MLP head
    gemmL(pAtt, m1_W, pH1, BN_TOT, 256, 256, 0,0,0,0, 0, m1_bias, 1, 0,0,0);
    cr_stats_partial<<<dim3(16, 1), 256>>>(pH1, BN_TOT, 256, 16);
    cr_stats_final<<<1, 256>>>(pMuL, pVaL, BN_TOT, 256, 16);
    gemmL(pH1, m2_W, pH2, BN_TOT, 256, 256, pMuL, pVaL, m1_g, m1_b, 0, m2_bias, 1, 0,0,0);
    cr_stats_partial<<<dim3(16, 1), 256>>>(pH2, BN_TOT, 256, 16);
    cr_stats_final<<<1, 256>>>(pMuL + 256, pVaL + 256, BN_TOT, 256, 16);
    cr_mlp3<<<BN_TOT/8, 256>>>(pH2, pMuL + 256, pVaL + 256, m2_g, m2_b, m3_W, m3_bias, out + BN_TOT*3);
}